// round 16
// baseline (speedup 1.0000x reference)
#include <cuda_runtime.h>
#include <math.h>

// Problem constants
#define BB 128
#define TT 512
#define DD 512
#define HH 512
#define KTOT 1024          // D + H (concatenated input+recurrent K)
#define NGATE 2048         // 4*H gate outputs per cell
#define NCTA 128           // persistent CTAs (<= SM count -> co-resident)

// Output section offsets in d_out (floats)
#define OUT_H    0ull
#define OUT_C    67108864ull           // 128*512*1024
#define OUT_HL   134217728ull          // + 128*512*1024
#define OUT_CL   134348800ull          // + 128*1024

// ---------------- device scratch (no allocation allowed) ----------------
__device__ float g_Wt[4][NGATE][KTOT];    // packed weights, gate-interleaved cols, k-contiguous
__device__ float g_bias[4][NGATE];        // combined biases (gate-interleaved)
__device__ float g_h[4][2][BB][HH];       // ping-pong h state per cell
__device__ float g_c[4][BB][HH];          // c state per cell
__device__ unsigned g_barGen = 0;         // grid barrier generation (monotone)
__device__ unsigned g_barCnt = 0;         // grid barrier arrival count (returns to 0)

struct Params {
    const float* wih[4];
    const float* whh[4];
    const float* bih[4];
    const float* bhh[4];
};

// ---------------- small helpers ----------------
__device__ __forceinline__ unsigned long long pk2(float lo, float hi) {
    unsigned long long r;
    asm("mov.b64 %0, {%1, %2};" : "=l"(r) : "f"(lo), "f"(hi));
    return r;
}
__device__ __forceinline__ void upk2(unsigned long long v, float& lo, float& hi) {
    asm("mov.b64 {%0, %1}, %2;" : "=f"(lo), "=f"(hi) : "l"(v));
}
__device__ __forceinline__ void fma2(unsigned long long& d, unsigned long long a,
                                     unsigned long long b) {
    asm("fma.rn.f32x2 %0, %1, %2, %0;" : "+l"(d) : "l"(a), "l"(b));
}
__device__ __forceinline__ void cp16(void* dst, const void* src) {
    unsigned sa = (unsigned)__cvta_generic_to_shared(dst);
    asm volatile("cp.async.cg.shared.global [%0], [%1], 16;" :: "r"(sa), "l"(src) : "memory");
}
__device__ __forceinline__ void cp_commit() {
    asm volatile("cp.async.commit_group;" ::: "memory");
}
__device__ __forceinline__ float sigf(float x) {
    return 1.0f / (1.0f + __expf(-x));
}

// ---------------- init / pack ----------------
__global__ void zero_state_kernel() {
    const int nh = 4 * 2 * BB * HH;
    const int nc = 4 * BB * HH;
    float* h = &g_h[0][0][0][0];
    float* c = &g_c[0][0][0];
    int stride = gridDim.x * blockDim.x;
    for (int i = blockIdx.x * blockDim.x + threadIdx.x; i < nh; i += stride) h[i] = 0.0f;
    for (int i = blockIdx.x * blockDim.x + threadIdx.x; i < nc; i += stride) c[i] = 0.0f;
}

// g_Wt[cell][j][k] with j = unit*4 + gate (gate-interleaved), k contiguous.
// Feature reversal of cell '0b' (cell index 1) folded into k for k < D.
__global__ void pack_kernel(Params p) {
    const long long total = 4ll * NGATE * KTOT;     // 8388608
    long long stride = (long long)gridDim.x * blockDim.x;
    float* wflat = &g_Wt[0][0][0];
    for (long long idx = (long long)blockIdx.x * blockDim.x + threadIdx.x; idx < total;
         idx += stride) {
        int cell = (int)(idx >> 21);            // / (2048*1024)
        int rem  = (int)(idx & ((1 << 21) - 1));
        int j = rem >> 10;                      // / 1024  (gate-interleaved col)
        int k = rem & (KTOT - 1);
        int u = j >> 2, gt = j & 3;
        int r = gt * HH + u;                    // original row in (4H, in)
        float v;
        if (k < DD) {
            int ks = (cell == 1) ? (DD - 1 - k) : k;   // fold feature-reversal of 0b
            v = p.wih[cell][r * DD + ks];
        } else {
            v = p.whh[cell][r * HH + (k - DD)];
        }
        wflat[idx] = v;
    }
    float* bflat = &g_bias[0][0];
    for (int idx = blockIdx.x * blockDim.x + threadIdx.x; idx < 4 * NGATE;
         idx += (int)stride) {
        int cell = idx >> 11;
        int j = idx & (NGATE - 1);
        int u = j >> 2, gt = j & 3;
        int r = gt * HH + u;
        bflat[idx] = p.bih[cell][r] + p.bhh[cell][r];
    }
}

// ---------------- grid barrier (replay-safe) ----------------
__device__ __forceinline__ void grid_barrier() {
    __syncthreads();
    if (threadIdx.x == 0) {
        volatile unsigned* vgen = &g_barGen;
        unsigned gen = *vgen;
        __threadfence();
        unsigned arrived = atomicAdd(&g_barCnt, 1u);
        if (arrived == NCTA - 1) {
            g_barCnt = 0;
            __threadfence();
            *vgen = gen + 1u;
        } else {
            while (*vgen == gen) { __nanosleep(64); }
        }
        __threadfence();
    }
    __syncthreads();
}

// ---------------- persistent fused LSTM ----------------
// 128 CTAs x 256 threads. Per (layer, step): each CTA owns one job =
// (cellLocal = blockIdx>>6, ntile = blockIdx&63): M=128 (full batch) x N=32
// gate-cols, K=1024 in double-buffered 32-k chunks.
// Thread tile 4m x 4n; fragments are LDS.128 with adjacent-k float pairs so
// fma.rn.f32x2 accumulates (even-k, odd-k) partial sums — no packing MOVs.
// XOR swizzle (col ^= ((row>>2)&7)<<2) keeps all fragment LDS conflict-free.
__global__ void __launch_bounds__(256, 1)
lstm_persistent_kernel(const float* __restrict__ x, float* __restrict__ out) {
    __shared__ float As[2][BB][32];   // [buf][m][k] swizzled, 128B rows
    __shared__ float Bs[2][32][32];   // [buf][n][k] swizzled

    const int tid = threadIdx.x;
    const int tx = tid & 7;           // n-group (unit)
    const int ty = tid >> 3;          // m-group (0..31)
    const int m0 = ty * 4;
    const int n0 = tx * 4;
    const int cellLocal = (int)(blockIdx.x >> 6);   // 0 or 1
    const int ntile = (int)(blockIdx.x & 63);
    const int jbase = ntile * 32;
    const int u = (jbase >> 2) + tx;  // unit index 0..511

    // per-thread constant swizzled fragment column offsets
    const int aswz = (ty & 7) << 2;
    const int bswz = tx << 2;

#pragma unroll 1
    for (int t = 0; t < TT; ++t) {
        const int pb = t & 1;         // buffer holding h_{t-1}
        const int cb = pb ^ 1;        // buffer receiving h_t
#pragma unroll 1
        for (int layer = 0; layer < 2; ++layer) {
            const int cellG = layer * 2 + cellLocal;
            const float* __restrict__ hprev = &g_h[cellG][pb][0][0];
            const float* __restrict__ hsrcL1 = &g_h[cellLocal][cb][0][0];
            const float* __restrict__ wcell = &g_Wt[cellG][0][0];

            // accumulators seeded with (bias, 0) — gate = lo + hi at epilogue
            unsigned long long acc[4][4];
            {
                const float4 bi = *reinterpret_cast<const float4*>(&g_bias[cellG][jbase + n0]);
#pragma unroll
                for (int i = 0; i < 4; ++i) {
                    acc[i][0] = pk2(bi.x, 0.0f);
                    acc[i][1] = pk2(bi.y, 0.0f);
                    acc[i][2] = pk2(bi.z, 0.0f);
                    acc[i][3] = pk2(bi.w, 0.0f);
                }
            }

            // ---- chunk loader (cp.async, swizzled stores) ----
            auto load_chunk = [&](int kc, int sb) {
                const int k0 = kc * 32;
                const float* aptr;
                long long astride;
                if (k0 < DD) {
                    if (layer == 0) { aptr = x + (long long)t * DD + k0; astride = (long long)TT * DD; }
                    else            { aptr = hsrcL1 + k0;                astride = HH; }
                } else {
                    aptr = hprev + (k0 - DD); astride = HH;
                }
#pragma unroll
                for (int i = 0; i < 4; ++i) {
                    int c = i * 256 + tid;             // 1024 16B chunks: 128 m x 8 kf
                    int m = c >> 3;
                    int kf = (c & 7) * 4;
                    int kd = kf ^ (((m >> 2) & 7) << 2);
                    cp16(&As[sb][m][kd], aptr + (long long)m * astride + kf);
                }
                {
                    int n = tid >> 3;                  // 256 16B chunks: 32 n x 8 kf
                    int kf = (tid & 7) * 4;
                    int kd = kf ^ (((n >> 2) & 7) << 2);
                    cp16(&Bs[sb][n][kd],
                         wcell + (long long)(jbase + n) * KTOT + k0 + kf);
                }
                cp_commit();
            };

            load_chunk(0, 0);

#pragma unroll 1
            for (int kc = 0; kc < 32; ++kc) {
                const int buf = kc & 1;
                if (kc + 1 < 32) {
                    load_chunk(kc + 1, buf ^ 1);
                    asm volatile("cp.async.wait_group 1;" ::: "memory");
                } else {
                    asm volatile("cp.async.wait_group 0;" ::: "memory");
                }
                __syncthreads();

#pragma unroll
                for (int kb = 0; kb < 32; kb += 4) {
                    const int acol = kb ^ aswz;
                    const int bcol = kb ^ bswz;
                    ulonglong2 av[4], bv[4];
#pragma unroll
                    for (int i = 0; i < 4; ++i)
                        av[i] = *reinterpret_cast<const ulonglong2*>(&As[buf][m0 + i][acol]);
#pragma unroll
                    for (int j = 0; j < 4; ++j)
                        bv[j] = *reinterpret_cast<const ulonglong2*>(&Bs[buf][n0 + j][bcol]);
#pragma unroll
                    for (int i = 0; i < 4; ++i) {
#pragma unroll
                        for (int j = 0; j < 4; ++j) {
                            fma2(acc[i][j], av[i].x, bv[j].x);   // k0,k1
                            fma2(acc[i][j], av[i].y, bv[j].y);   // k2,k3
                        }
                    }
                }
                __syncthreads();
            }

            // ---- epilogue: LSTM pointwise (thread owns 4 batches x 1 unit) ----
#pragma unroll
            for (int r = 0; r < 4; ++r) {
                const int m = m0 + r;
                float lo, hi;
                upk2(acc[r][0], lo, hi); float gi = lo + hi;
                upk2(acc[r][1], lo, hi); float gf = lo + hi;
                upk2(acc[r][2], lo, hi); float gg = lo + hi;
                upk2(acc[r][3], lo, hi); float go = lo + hi;
                float iv = sigf(gi);
                float fv = sigf(gf);
                float gv = tanhf(gg);
                float ov = sigf(go);
                float cpv = g_c[cellG][m][u];
                float c2 = fv * cpv + iv * gv;
                float h2 = ov * tanhf(c2);
                g_c[cellG][m][u] = c2;
                g_h[cellG][cb][m][u] = h2;
                if (layer == 1) {
                    const int n = u + cellLocal * HH;
                    const unsigned long long ob =
                        ((unsigned long long)m * TT + (unsigned)t) * 1024ull + (unsigned)n;
                    out[OUT_H + ob] = h2;
                    out[OUT_C + ob] = c2;
                    if (t == TT - 1) {
                        const unsigned long long lb = (unsigned long long)m * 1024ull + (unsigned)n;
                        out[OUT_HL + lb] = h2;
                        out[OUT_CL + lb] = c2;
                    }
                }
            }

            grid_barrier();
        }
    }
}

// ---------------- launcher (3 graph nodes) ----------------
extern "C" void kernel_launch(void* const* d_in, const int* in_sizes, int n_in,
                              void* d_out, int out_size) {
    const float* x = (const float*)d_in[0];
    Params p;
    for (int c = 0; c < 4; ++c) {
        p.wih[c] = (const float*)d_in[1 + 4 * c];
        p.whh[c] = (const float*)d_in[2 + 4 * c];
        p.bih[c] = (const float*)d_in[3 + 4 * c];
        p.bhh[c] = (const float*)d_in[4 + 4 * c];
    }
    float* out = (float*)d_out;

    zero_state_kernel<<<256, 256>>>();
    pack_kernel<<<4096, 256>>>(p);
    lstm_persistent_kernel<<<NCTA, 256>>>(x, out);
}